// round 15
// baseline (speedup 1.0000x reference)
#include <cuda_runtime.h>
#include <cuda_bf16.h>
#include <math.h>
#include <stdint.h>

// ---------------- problem constants ----------------
#define NN    50000
#define HH    128
#define EE    1000000
#define FF1   147
#define FF2   21
#define GG    512
#define EPSV  1e-5f

// ---------------- device scratch (no allocs allowed) ----------------
__device__ float g_xh  [NN*HH];
__device__ float g_agg1[NN*HH];
__device__ float g_agg2[NN*HH];
__device__ float g_tmp [NN*HH];
__device__ float g_h1  [NN*HH];
__device__ float g_h2  [NN*HH];
__device__ float g_hA  [NN*HH];
__device__ float g_hB  [NN*HH];
__device__ float g_gsum[GG*HH];   // later: O plane
__device__ float g_gvar[GG*HH];   // later: S plane
__device__ float g_gcnt[GG];

// ================= warp-MMA helpers (baseline PTX, sm_80+) =================
__device__ __forceinline__ void mma_bf16(float d[4], const uint32_t a[4], const uint32_t b[2]) {
    asm volatile(
        "mma.sync.aligned.m16n8k16.row.col.f32.bf16.bf16.f32 "
        "{%0,%1,%2,%3}, {%4,%5,%6,%7}, {%8,%9}, {%0,%1,%2,%3};"
        : "+f"(d[0]), "+f"(d[1]), "+f"(d[2]), "+f"(d[3])
        : "r"(a[0]), "r"(a[1]), "r"(a[2]), "r"(a[3]), "r"(b[0]), "r"(b[1]));
}

__device__ __forceinline__ void ldsm4(uint32_t r[4], uint32_t addr) {
    asm volatile("ldmatrix.sync.aligned.m8n8.x4.shared.b16 {%0,%1,%2,%3}, [%4];"
        : "=r"(r[0]), "=r"(r[1]), "=r"(r[2]), "=r"(r[3]) : "r"(addr));
}

__device__ __forceinline__ uint32_t smaddr(const void* p) {
    return (uint32_t)__cvta_generic_to_shared(p);
}

__device__ __forceinline__ void red_add_v2(float* p, float2 v) {
    asm volatile("red.global.add.v2.f32 [%0], {%1,%2};"
        :: "l"(p), "f"(v.x), "f"(v.y) : "memory");
}

// ---- fast truncation-based split: hi = top 16 bits (exact bf16), lo = bf16(f - hi).
// f = hi + lo up to 2^-17 rel residue; dropped AlBl term <= 2^-16 rel (as before).
__device__ __forceinline__ void fsplit2(float f0, float f1, uint32_t& hi, uint32_t& lo) {
    uint32_t u0 = __float_as_uint(f0), u1 = __float_as_uint(f1);
    hi = __byte_perm(u0, u1, 0x7632);                    // [bf16(f0), bf16(f1)]
    float l0 = f0 - __uint_as_float(u0 & 0xFFFF0000u);
    float l1 = f1 - __uint_as_float(u1 & 0xFFFF0000u);
    asm("cvt.rn.bf16x2.f32 %0, %1, %2;" : "=r"(lo) : "f"(l1), "f"(l0));
}

__device__ __forceinline__ void fsplit1(float f, uint16_t& h, uint16_t& l) {
    uint32_t u = __float_as_uint(f);
    h = (uint16_t)(u >> 16);
    float lf = f - __uint_as_float(u & 0xFFFF0000u);
    l = (uint16_t)__bfloat16_as_ushort(__float2bfloat16_rn(lf));
}

#define OFF_A(lane, stride) ((((lane) & 15) * (stride) + (((lane) >> 4) << 3)) * 2)
#define OFF_B(lane, stride) (((((lane) & 7) + (((lane) >> 4) << 3)) * (stride) + ((((lane) >> 3) & 1) << 3)) * 2)

// ---------------- edge kernel smem layout ----------------
template<int F> struct EL {
    static constexpr int KP  = (F + 15) & ~15;
    static constexpr int SA  = KP + 8;
    static constexpr int W1H = 0;
    static constexpr int W1L = W1H + 64 * SA * 2;
    static constexpr int W2H = W1L + 64 * SA * 2;
    static constexpr int W2L = W2H + 128 * 72 * 2;
    static constexpr int MIH = W2L + 128 * 72 * 2;
    static constexpr int MIL = MIH + 128 * 72 * 2;
    static constexpr int A1H = MIL + 128 * 72 * 2;
    static constexpr int A1L = A1H + 128 * SA * 2;
    static constexpr int IDX = A1L + 128 * SA * 2;
    static constexpr int TOT = IDX + 2048;
};

// ================= fused edge kernel (paired staging + fsplit) =================
template<int F, int NTHR, int MINB>
__global__ void __launch_bounds__(NTHR, MINB) edge_fused(
    const float* __restrict__ feat, const float* __restrict__ w1,
    const float* __restrict__ w2,   const float* __restrict__ xh,
    const int* __restrict__ src,    const int* __restrict__ dst,
    float* __restrict__ agg, int ntiles)
{
    using L = EL<F>;
    constexpr int MW = NTHR / 64;
    constexpr int RM = 128 / MW;
    constexpr int MT = RM / 16;
    constexpr int SL = (F + 1) / 2;    // k-pair slots per row (last may be single)

    extern __shared__ char smem[];
    __nv_bfloat16* w1h = (__nv_bfloat16*)(smem + L::W1H);
    __nv_bfloat16* w1l = (__nv_bfloat16*)(smem + L::W1L);
    __nv_bfloat16* w2h = (__nv_bfloat16*)(smem + L::W2H);
    __nv_bfloat16* w2l = (__nv_bfloat16*)(smem + L::W2L);
    __nv_bfloat16* mih = (__nv_bfloat16*)(smem + L::MIH);
    __nv_bfloat16* mil = (__nv_bfloat16*)(smem + L::MIL);
    __nv_bfloat16* a1h = (__nv_bfloat16*)(smem + L::A1H);
    __nv_bfloat16* a1l = (__nv_bfloat16*)(smem + L::A1L);
    int*           sidx= (int*)          (smem + L::IDX);

    const int tid  = threadIdx.x;
    const int wid  = tid >> 5, lane = tid & 31;
    const int g    = lane >> 2, tq = lane & 3;
    const int wm   = wid & (MW - 1), wn = wid / MW;

    const uint32_t bA1h = smaddr(a1h), bA1l = smaddr(a1l);
    const uint32_t bW1h = smaddr(w1h), bW1l = smaddr(w1l);
    const uint32_t bW2h = smaddr(w2h), bW2l = smaddr(w2l);
    const uint32_t bMih = smaddr(mih), bMil = smaddr(mil);
    const int oA_SA = OFF_A(lane, L::SA), oB_SA = OFF_B(lane, L::SA);
    const int oA_72 = OFF_A(lane, 72),    oB_72 = OFF_B(lane, 72);

    for (int i = tid; i < L::TOT / 4; i += NTHR)
        reinterpret_cast<uint32_t*>(smem)[i] = 0;
    __syncthreads();

    // w1 staging: k-paired (k, k+1) -> STS.32; k+1 >= F padded with 0 (pad stays 0)
    for (int i = tid; i < 64 * SL; i += NTHR) {
        int n = i & 63, k = (i >> 6) * 2;
        float f0 = w1[k * 64 + n];
        float f1 = (k + 1 < F) ? w1[(k + 1) * 64 + n] : 0.f;
        uint32_t hi, lo; fsplit2(f0, f1, hi, lo);
        *reinterpret_cast<uint32_t*>(&w1h[n * L::SA + k]) = hi;
        *reinterpret_cast<uint32_t*>(&w1l[n * L::SA + k]) = lo;
    }
    for (int i = tid; i < 32 * 128; i += NTHR) {
        int n = i & 127, k = (i >> 7) * 2;
        uint32_t hi, lo;
        fsplit2(w2[k * 128 + n], w2[(k + 1) * 128 + n], hi, lo);
        *reinterpret_cast<uint32_t*>(&w2h[n * 72 + k]) = hi;
        *reinterpret_cast<uint32_t*>(&w2l[n * 72 + k]) = lo;
    }

    auto stage = [&](int tt, int parity) {
        if (tt >= ntiles) return;
        const int se0 = tt * 128;
        const int scnt = min(128, EE - se0);
        const float* fb = feat + (size_t)se0 * F;
        int* sx = sidx + parity * 256;
        if (scnt == 128) {
            constexpr int NIT = (128 * SL + NTHR - 1) / NTHR;
            #pragma unroll
            for (int jj = 0; jj < NIT; ++jj) {
                int i = tid + jj * NTHR;
                if ((128 * SL) % NTHR == 0 || i < 128 * SL) {
                    int e = i / SL, j = i - e * SL, k = j * 2;
                    if (k + 1 < F) {
                        uint32_t hi, lo;
                        fsplit2(fb[e * F + k], fb[e * F + k + 1], hi, lo);
                        *reinterpret_cast<uint32_t*>(&a1h[e * L::SA + k]) = hi;
                        *reinterpret_cast<uint32_t*>(&a1l[e * L::SA + k]) = lo;
                    } else {
                        uint16_t h, l; fsplit1(fb[e * F + k], h, l);
                        *reinterpret_cast<uint16_t*>(&a1h[e * L::SA + k]) = h;
                        *reinterpret_cast<uint16_t*>(&a1l[e * L::SA + k]) = l;
                    }
                }
            }
            if (tid < 128) { sx[tid] = src[se0 + tid]; sx[128 + tid] = dst[se0 + tid]; }
        } else {
            for (int i = tid; i < scnt * F; i += NTHR) {
                int e = i / F, k = i - e * F;
                uint16_t h, l; fsplit1(fb[i], h, l);
                *reinterpret_cast<uint16_t*>(&a1h[e * L::SA + k]) = h;
                *reinterpret_cast<uint16_t*>(&a1l[e * L::SA + k]) = l;
            }
            if (tid < scnt) { sx[tid] = src[se0 + tid]; sx[128 + tid] = dst[se0 + tid]; }
        }
    };

    int t = blockIdx.x, pb = 0;
    stage(t, 0);
    __syncthreads();

    for (; t < ntiles; t += gridDim.x) {
        const int cnt = min(128, EE - t * 128);
        const int* sx = sidx + pb * 256;

        // ---- GEMM1 ----
        {
            const int mo = wm * RM, no = wn * 32;
            float acc[MT][4][4];
            #pragma unroll
            for (int a = 0; a < MT; ++a)
                #pragma unroll
                for (int b = 0; b < 4; ++b)
                    #pragma unroll
                    for (int c = 0; c < 4; ++c) acc[a][b][c] = 0.f;

            #pragma unroll
            for (int ko = 0; ko < L::KP; ko += 16) {
                uint32_t Ah[MT][4], Al[MT][4];
                #pragma unroll
                for (int mt = 0; mt < MT; ++mt) {
                    const int rb2 = ((mo + mt*16) * L::SA + ko) * 2;
                    ldsm4(Ah[mt], bA1h + rb2 + oA_SA);
                    ldsm4(Al[mt], bA1l + rb2 + oA_SA);
                }
                uint32_t Bh[4][2], Bl[4][2];
                #pragma unroll
                for (int p = 0; p < 2; ++p) {
                    const int nb2 = ((no + p*16) * L::SA + ko) * 2;
                    uint32_t tr[4];
                    ldsm4(tr, bW1h + nb2 + oB_SA);
                    Bh[2*p][0]=tr[0]; Bh[2*p][1]=tr[1]; Bh[2*p+1][0]=tr[2]; Bh[2*p+1][1]=tr[3];
                    ldsm4(tr, bW1l + nb2 + oB_SA);
                    Bl[2*p][0]=tr[0]; Bl[2*p][1]=tr[1]; Bl[2*p+1][0]=tr[2]; Bl[2*p+1][1]=tr[3];
                }
                #pragma unroll
                for (int nt = 0; nt < 4; ++nt)
                    #pragma unroll
                    for (int mt = 0; mt < MT; ++mt) {
                        mma_bf16(acc[mt][nt], Ah[mt], Bh[nt]);
                        mma_bf16(acc[mt][nt], Ah[mt], Bl[nt]);
                        mma_bf16(acc[mt][nt], Al[mt], Bh[nt]);
                    }
            }
            #pragma unroll
            for (int mt = 0; mt < MT; ++mt)
                #pragma unroll
                for (int nt = 0; nt < 4; ++nt) {
                    int r0 = mo + mt*16 + g, col = no + nt*8 + tq*2;
                    uint32_t hi, lo;
                    fsplit2(acc[mt][nt][0], acc[mt][nt][1], hi, lo);
                    *reinterpret_cast<uint32_t*>(&mih[r0*72 + col]) = hi;
                    *reinterpret_cast<uint32_t*>(&mil[r0*72 + col]) = lo;
                    fsplit2(acc[mt][nt][2], acc[mt][nt][3], hi, lo);
                    *reinterpret_cast<uint32_t*>(&mih[(r0+8)*72 + col]) = hi;
                    *reinterpret_cast<uint32_t*>(&mil[(r0+8)*72 + col]) = lo;
                }
        }
        __syncthreads();

        // ---- GEMM2 (K=64) ----
        float acc[MT][8][4];
        {
            const int mo = wm * RM, no = wn * 64;
            #pragma unroll
            for (int a = 0; a < MT; ++a)
                #pragma unroll
                for (int b = 0; b < 8; ++b)
                    #pragma unroll
                    for (int c = 0; c < 4; ++c) acc[a][b][c] = 0.f;

            #pragma unroll
            for (int ko = 0; ko < 64; ko += 16) {
                uint32_t Ah[MT][4], Al[MT][4];
                #pragma unroll
                for (int mt = 0; mt < MT; ++mt) {
                    const int rb2 = ((mo + mt*16) * 72 + ko) * 2;
                    ldsm4(Ah[mt], bMih + rb2 + oA_72);
                    ldsm4(Al[mt], bMil + rb2 + oA_72);
                }
                uint32_t Bh[8][2], Bl[8][2];
                #pragma unroll
                for (int p = 0; p < 4; ++p) {
                    const int nb2 = ((no + p*16) * 72 + ko) * 2;
                    uint32_t tr[4];
                    ldsm4(tr, bW2h + nb2 + oB_72);
                    Bh[2*p][0]=tr[0]; Bh[2*p][1]=tr[1]; Bh[2*p+1][0]=tr[2]; Bh[2*p+1][1]=tr[3];
                    ldsm4(tr, bW2l + nb2 + oB_72);
                    Bl[2*p][0]=tr[0]; Bl[2*p][1]=tr[1]; Bl[2*p+1][0]=tr[2]; Bl[2*p+1][1]=tr[3];
                }
                #pragma unroll
                for (int nt = 0; nt < 8; ++nt)
                    #pragma unroll
                    for (int mt = 0; mt < MT; ++mt) {
                        mma_bf16(acc[mt][nt], Ah[mt], Bh[nt]);
                        mma_bf16(acc[mt][nt], Ah[mt], Bl[nt]);
                        mma_bf16(acc[mt][nt], Al[mt], Bh[nt]);
                    }
            }
        }

        // ---- direct register epilogue ----
        {
            const int no = wn * 64, cb = no + tq * 2;
            #pragma unroll
            for (int mt = 0; mt < MT; ++mt) {
                #pragma unroll
                for (int hf = 0; hf < 2; ++hf) {
                    int e = wm * RM + mt*16 + g + hf*8;
                    if (e < cnt) {
                        int s = sx[e], d = sx[128 + e];
                        const float* xrow = xh + (size_t)s * 128 + cb;
                        float* arow = agg + (size_t)d * 128 + cb;
                        float2 xv[8];
                        #pragma unroll
                        for (int nt = 0; nt < 8; ++nt)
                            xv[nt] = *reinterpret_cast<const float2*>(xrow + nt*8);
                        #pragma unroll
                        for (int nt = 0; nt < 8; ++nt)
                            red_add_v2(arow + nt*8,
                                make_float2(acc[mt][nt][hf*2] * xv[nt].x,
                                            acc[mt][nt][hf*2+1] * xv[nt].y));
                    }
                }
            }
        }

        stage(t + gridDim.x, pb ^ 1);
        __syncthreads();
        pb ^= 1;
    }
}

// ================= node GEMM on HMMA (GN = fused S*h+O affine in staging) ====
template<bool HAS_A2, bool ACT, bool HAS_RES, bool DB, bool GN>
__global__ void __launch_bounds__(512) node_hmma(
    const float* __restrict__ A,  const float* __restrict__ W,
    const float* __restrict__ A2, const float* __restrict__ W2,
    const float* __restrict__ bias, const float* __restrict__ res,
    const int* __restrict__ batchv, const float* __restrict__ Spl,
    const float* __restrict__ Opl,
    float* __restrict__ out, int nrows, int ntiles)
{
    static_assert(!(HAS_A2 && DB), "DB only for single-A variant");
    constexpr int WS = 128 * 136 * 2;
    constexpr int NWP = HAS_A2 ? 4 : 2;
    constexpr int NAP = DB ? 4 : 2;
    extern __shared__ char smem[];
    __nv_bfloat16* wh  = (__nv_bfloat16*)(smem);
    __nv_bfloat16* wl  = (__nv_bfloat16*)(smem + WS);
    __nv_bfloat16* w2h = (__nv_bfloat16*)(smem + 2 * WS);
    __nv_bfloat16* w2l = (__nv_bfloat16*)(smem + 3 * WS);
    float*         bs  = (float*)        (smem + (NWP + NAP) * WS);

    const int tid = threadIdx.x;
    const int wid = tid >> 5, lane = tid & 31;
    const int g = lane >> 2, tq = lane & 3;
    const int wm = wid & 7, wn = wid >> 3;
    const int mo = wm * 16, no = wn * 64;
    const int oA = OFF_A(lane, 136), oB = OFF_B(lane, 136);

    for (int i = tid; i < 64 * 128; i += 512) {
        int n = i & 127, k = (i >> 7) * 2;
        uint32_t hi, lo;
        fsplit2(W[k * 128 + n], W[(k + 1) * 128 + n], hi, lo);
        *reinterpret_cast<uint32_t*>(&wh[n * 136 + k]) = hi;
        *reinterpret_cast<uint32_t*>(&wl[n * 136 + k]) = lo;
        if (HAS_A2) {
            fsplit2(W2[k * 128 + n], W2[(k + 1) * 128 + n], hi, lo);
            *reinterpret_cast<uint32_t*>(&w2h[n * 136 + k]) = hi;
            *reinterpret_cast<uint32_t*>(&w2l[n * 136 + k]) = lo;
        }
    }
    if (tid < 128) bs[tid] = bias[tid];

    auto a_hi = [&](int p) { return (__nv_bfloat16*)(smem + (NWP + p * 2) * WS); };
    auto a_lo = [&](int p) { return (__nv_bfloat16*)(smem + (NWP + p * 2 + 1) * WS); };

    auto stageA = [&](const float* __restrict__ src_, int tt, int p) {
        if (tt >= ntiles) return;
        const int rb = tt * 128;
        __nv_bfloat16* dh = a_hi(p);
        __nv_bfloat16* dl = a_lo(p);
        #pragma unroll 8
        for (int i = tid; i < 128 * 64; i += 512) {
            int e = i >> 6, kp = (i & 63) * 2;
            int r = rb + e;
            float2 v = (r < nrows) ? *reinterpret_cast<const float2*>(&src_[(size_t)r * 128 + kp])
                                   : make_float2(0.f, 0.f);
            if (GN) {
                if (r < nrows) {
                    int b = batchv[r];
                    float2 Sv = *reinterpret_cast<const float2*>(&Spl[b * 128 + kp]);
                    float2 Ov = *reinterpret_cast<const float2*>(&Opl[b * 128 + kp]);
                    v.x = Sv.x * v.x + Ov.x;
                    v.y = Sv.y * v.y + Ov.y;
                }
            }
            uint32_t hi, lo; fsplit2(v.x, v.y, hi, lo);
            *reinterpret_cast<uint32_t*>(&dh[e * 136 + kp]) = hi;
            *reinterpret_cast<uint32_t*>(&dl[e * 136 + kp]) = lo;
        }
    };

    auto run_mma = [&](float acc[8][4], const __nv_bfloat16* ahp, const __nv_bfloat16* alp,
                       const __nv_bfloat16* bhp, const __nv_bfloat16* blp) {
        const uint32_t bAh = smaddr(ahp), bAl = smaddr(alp);
        const uint32_t bBh = smaddr(bhp), bBl = smaddr(blp);
        #pragma unroll
        for (int ko = 0; ko < 128; ko += 16) {
            uint32_t Ah[4], Al[4];
            const int rb2 = (mo * 136 + ko) * 2;
            ldsm4(Ah, bAh + rb2 + oA);
            ldsm4(Al, bAl + rb2 + oA);
            #pragma unroll
            for (int p = 0; p < 4; ++p) {
                const int nb2 = ((no + p*16) * 136 + ko) * 2;
                uint32_t th[4], tl[4];
                ldsm4(th, bBh + nb2 + oB);
                ldsm4(tl, bBl + nb2 + oB);
                uint32_t B0h[2] = {th[0], th[1]}, B1h[2] = {th[2], th[3]};
                uint32_t B0l[2] = {tl[0], tl[1]}, B1l[2] = {tl[2], tl[3]};
                mma_bf16(acc[2*p],   Ah, B0h);
                mma_bf16(acc[2*p],   Ah, B0l);
                mma_bf16(acc[2*p],   Al, B0h);
                mma_bf16(acc[2*p+1], Ah, B1h);
                mma_bf16(acc[2*p+1], Ah, B1l);
                mma_bf16(acc[2*p+1], Al, B1h);
            }
        }
    };

    auto epilogue = [&](float acc[8][4], int rb) {
        #pragma unroll
        for (int nt = 0; nt < 8; ++nt) {
            const int c = no + nt*8 + tq*2;
            const float b0 = bs[c], b1 = bs[c + 1];
            #pragma unroll
            for (int half = 0; half < 2; ++half) {
                int r = rb + mo + g + half*8;
                if (r < nrows) {
                    float v0 = acc[nt][half*2]     + b0;
                    float v1 = acc[nt][half*2 + 1] + b1;
                    if (ACT) { v0 = v0 / (1.f + expf(-v0)); v1 = v1 / (1.f + expf(-v1)); }
                    if (HAS_RES) {
                        float2 rr = *reinterpret_cast<const float2*>(&res[(size_t)r*128 + c]);
                        v0 += rr.x; v1 += rr.y;
                    }
                    *reinterpret_cast<float2*>(&out[(size_t)r*128 + c]) = make_float2(v0, v1);
                }
            }
        }
    };

    if (DB) {
        int t = blockIdx.x, pb = 0;
        stageA(A, t, 0);
        __syncthreads();
        for (; t < ntiles; t += gridDim.x) {
            float acc[8][4];
            #pragma unroll
            for (int b = 0; b < 8; ++b)
                #pragma unroll
                for (int c = 0; c < 4; ++c) acc[b][c] = 0.f;
            run_mma(acc, a_hi(pb), a_lo(pb), wh, wl);
            stageA(A, t + gridDim.x, pb ^ 1);
            epilogue(acc, t * 128);
            pb ^= 1;
            __syncthreads();
        }
    } else {
        __syncthreads();
        for (int t = blockIdx.x; t < ntiles; t += gridDim.x) {
            stageA(A, t, 0);
            __syncthreads();
            float acc[8][4];
            #pragma unroll
            for (int b = 0; b < 8; ++b)
                #pragma unroll
                for (int c = 0; c < 4; ++c) acc[b][c] = 0.f;
            run_mma(acc, a_hi(0), a_lo(0), wh, wl);
            if (HAS_A2) {
                __syncthreads();
                stageA(A2, t, 0);
                __syncthreads();
                run_mma(acc, a_hi(0), a_lo(0), w2h, w2l);
            }
            epilogue(acc, t * 128);
            __syncthreads();
        }
    }
}

// ---------------- zero init ----------------
__global__ void zero_bufs_kernel() {
    int idx = blockIdx.x * blockDim.x + threadIdx.x;
    if (idx < NN*HH) { g_agg1[idx] = 0.f; g_agg2[idx] = 0.f; }
    if (idx < GG*HH) { g_gsum[idx] = 0.f; g_gvar[idx] = 0.f; }
    if (idx < GG)    { g_gcnt[idx] = 0.f; }
}

// ---------------- GraphNorm: segmented reductions (batch is sorted) ----------------
__global__ void __launch_bounds__(128) gn_accum_seg(
    const float* __restrict__ h, const int* __restrict__ batch)
{
    const int n0 = blockIdx.x * 64;
    const int c  = threadIdx.x;
    const int nend = min(n0 + 64, NN);
    int   cur = batch[n0];
    float run = 0.f, runc = 0.f;
    for (int n = n0; n < nend; ++n) {
        int b = batch[n];
        if (b != cur) {
            atomicAdd(&g_gsum[cur*128 + c], run);
            if (c == 0) atomicAdd(&g_gcnt[cur], runc);
            run = 0.f; runc = 0.f; cur = b;
        }
        run  += h[(size_t)n*128 + c];
        runc += 1.f;
    }
    atomicAdd(&g_gsum[cur*128 + c], run);
    if (c == 0) atomicAdd(&g_gcnt[cur], runc);
}

__global__ void __launch_bounds__(128) gn_var_seg(
    const float* __restrict__ h, const int* __restrict__ batch,
    const float* __restrict__ ms)
{
    const int n0 = blockIdx.x * 64;
    const int c  = threadIdx.x;
    const int nend = min(n0 + 64, NN);
    const float msc = ms[c];
    int   cur = batch[n0];
    float mean = g_gsum[cur*128 + c] / fmaxf(g_gcnt[cur], 1.f);
    float run = 0.f;
    for (int n = n0; n < nend; ++n) {
        int b = batch[n];
        if (b != cur) {
            atomicAdd(&g_gvar[cur*128 + c], run);
            run = 0.f; cur = b;
            mean = g_gsum[cur*128 + c] / fmaxf(g_gcnt[cur], 1.f);
        }
        float o = h[(size_t)n*128 + c] - mean * msc;
        run += o * o;
    }
    atomicAdd(&g_gvar[cur*128 + c], run);
}

__global__ void gn_affine(const float* __restrict__ ms,
                          const float* __restrict__ nw, const float* __restrict__ nb)
{
    int idx = blockIdx.x * blockDim.x + threadIdx.x;
    if (idx >= GG*HH) return;
    int b = idx >> 7, c = idx & 127;
    float cnt  = fmaxf(g_gcnt[b], 1.f);
    float mean = g_gsum[idx] / cnt;
    float istd = rsqrtf(g_gvar[idx] / cnt + EPSV);
    float S = nw[c] * istd;
    g_gvar[idx] = S;
    g_gsum[idx] = nb[c] - S * mean * ms[c];
}

// ---------------- host launcher ----------------
static inline void set_smem(const void* f, int bytes) {
    cudaFuncSetAttribute(f, cudaFuncAttributeMaxDynamicSharedMemorySize, bytes);
}

extern "C" void kernel_launch(void* const* d_in, const int* in_sizes, int n_in,
                              void* d_out, int out_size) {
    (void)in_sizes; (void)n_in; (void)out_size;

    const float* x          = (const float*)d_in[0];
    const float* feature1   = (const float*)d_in[1];
    const float* feature2   = (const float*)d_in[2];
    const int*   edge_index = (const int*)  d_in[3];
    const int*   batch      = (const int*)  d_in[4];
    const float* lin_w      = (const float*)d_in[5];
    const float* lin_b      = (const float*)d_in[6];
    const float* f1_w1      = (const float*)d_in[7];
    const float* f1_w2      = (const float*)d_in[8];
    const float* f2_w1      = (const float*)d_in[9];
    const float* f2_w2      = (const float*)d_in[10];
    const float* c1_rel_w   = (const float*)d_in[11];
    const float* c1_rel_b   = (const float*)d_in[12];
    const float* c1_root_w  = (const float*)d_in[13];
    const float* c2_rel_w   = (const float*)d_in[14];
    const float* c2_rel_b   = (const float*)d_in[15];
    const float* c2_root_w  = (const float*)d_in[16];
    const float* lin1_w     = (const float*)d_in[17];
    const float* lin1_b     = (const float*)d_in[18];
    const float* lin2_w     = (const float*)d_in[19];
    const float* lin2_b     = (const float*)d_in[20];
    const float* lincat_w   = (const float*)d_in[21];
    const float* lincat_b   = (const float*)d_in[22];
    const float* norm_w     = (const float*)d_in[23];
    const float* norm_b     = (const float*)d_in[24];
    const float* norm_ms    = (const float*)d_in[25];
    const float* lins_w     = (const float*)d_in[26];
    const float* lins_b     = (const float*)d_in[27];
    const float* final_w    = (const float*)d_in[28];
    const float* final_b    = (const float*)d_in[29];
    float* out = (float*)d_out;

    const int* src = edge_index;
    const int* dst = edge_index + EE;

    float *xh, *agg1, *agg2, *tmp, *h1, *h2, *hA, *hB, *gvar, *gsum;
    cudaGetSymbolAddress((void**)&xh,   g_xh);
    cudaGetSymbolAddress((void**)&agg1, g_agg1);
    cudaGetSymbolAddress((void**)&agg2, g_agg2);
    cudaGetSymbolAddress((void**)&tmp,  g_tmp);
    cudaGetSymbolAddress((void**)&h1,   g_h1);
    cudaGetSymbolAddress((void**)&h2,   g_h2);
    cudaGetSymbolAddress((void**)&hA,   g_hA);
    cudaGetSymbolAddress((void**)&hB,   g_hB);
    cudaGetSymbolAddress((void**)&gvar, g_gvar);
    cudaGetSymbolAddress((void**)&gsum, g_gsum);

    constexpr int WS = 128 * 136 * 2;
    const int N1 = 6 * WS + 512;
    const int N2 = 6 * WS + 512;

    set_smem((const void*)node_hmma<false,true ,false,true ,false>, N1);
    set_smem((const void*)node_hmma<false,true ,true ,true ,false>, N1);
    set_smem((const void*)node_hmma<false,false,false,true ,true >, N1);
    set_smem((const void*)node_hmma<true ,false,false,false,false>, N2);
    set_smem((const void*)node_hmma<true ,false,true ,false,false>, N2);
    set_smem((const void*)edge_fused<FF1,512,1>, EL<FF1>::TOT);
    set_smem((const void*)edge_fused<FF2,256,2>, EL<FF2>::TOT);

    const int EL_GRID = (NN*HH + 255) / 256;
    const int GH_GRID = (GG*HH + 255) / 256;
    const int SEG_GRID = (NN + 63) / 64;
    const int NT      = (EE + 127) / 128;
    const int NTN     = (NN + 127) / 128;

    // 0) zero accumulators
    zero_bufs_kernel<<<EL_GRID, 256>>>();

    // 1) xh = swish(x @ lin_w + lin_b)
    node_hmma<false,true,false,true,false><<<148, 512, N1>>>(
        x, lin_w, nullptr, nullptr, lin_b, nullptr,
        nullptr, nullptr, nullptr, xh, NN, NTN);

    // 2) fused edge messages
    edge_fused<FF1,512,1><<<148, 512, EL<FF1>::TOT>>>(feature1, f1_w1, f1_w2, xh, src, dst, agg1, NT);
    edge_fused<FF2,256,2><<<296, 256, EL<FF2>::TOT>>>(feature2, f2_w1, f2_w2, xh, src, dst, agg2, NT);

    // 3) conv1
    node_hmma<true,false,false,false,false><<<148, 512, N2>>>(
        agg1, c1_rel_w, xh, c1_root_w, c1_rel_b, nullptr,
        nullptr, nullptr, nullptr, tmp, NN, NTN);
    node_hmma<false,true,false,true,false><<<148, 512, N1>>>(
        tmp, lin1_w, nullptr, nullptr, lin1_b, nullptr,
        nullptr, nullptr, nullptr, h1, NN, NTN);

    // 4) conv2
    node_hmma<true,false,false,false,false><<<148, 512, N2>>>(
        agg2, c2_rel_w, xh, c2_root_w, c2_rel_b, nullptr,
        nullptr, nullptr, nullptr, tmp, NN, NTN);
    node_hmma<false,true,false,true,false><<<148, 512, N1>>>(
        tmp, lin2_w, nullptr, nullptr, lin2_b, nullptr,
        nullptr, nullptr, nullptr, h2, NN, NTN);

    // 5) hA = h1@Wtop + h2@Wbot + lincat_b + xh
    node_hmma<true,false,true,false,false><<<148, 512, N2>>>(
        h1, lincat_w, h2, lincat_w + 128*128, lincat_b, xh,
        nullptr, nullptr, nullptr, hA, NN, NTN);

    // 6) residual stack
    node_hmma<false,true,true,true,false><<<148, 512, N1>>>(
        hA, lins_w + 0*16384, nullptr, nullptr, lins_b + 0*128, hA,
        nullptr, nullptr, nullptr, hB, NN, NTN);
    node_hmma<false,true,true,true,false><<<148, 512, N1>>>(
        hB, lins_w + 1*16384, nullptr, nullptr, lins_b + 1*128, hB,
        nullptr, nullptr, nullptr, hA, NN, NTN);
    node_hmma<false,true,true,true,false><<<148, 512, N1>>>(
        hA, lins_w + 2*16384, nullptr, nullptr, lins_b + 2*128, hA,
        nullptr, nullptr, nullptr, hB, NN, NTN);

    // 7) GraphNorm on hB (segmented; folded into per-(graph,col) affine)
    gn_accum_seg<<<SEG_GRID, 128>>>(hB, batch);
    gn_var_seg  <<<SEG_GRID, 128>>>(hB, batch, norm_ms);
    gn_affine   <<<GH_GRID, 256>>>(norm_ms, norm_w, norm_b);

    // 8) out = (S*hB + O) @ final_w + final_b
    node_hmma<false,false,false,true,true><<<148, 512, N1>>>(
        hB, final_w, nullptr, nullptr, final_b, nullptr,
        batch, gvar, gsum, out, NN, NTN);
}

// round 16
// speedup vs baseline: 1.0600x; 1.0600x over previous
#include <cuda_runtime.h>
#include <cuda_bf16.h>
#include <math.h>
#include <stdint.h>

// ---------------- problem constants ----------------
#define NN    50000
#define HH    128
#define EE    1000000
#define FF1   147
#define FF2   21
#define GG    512
#define EPSV  1e-5f

// ---------------- device scratch (no allocs allowed) ----------------
__device__ float g_xh  [NN*HH];
__device__ float g_agg1[NN*HH];
__device__ float g_agg2[NN*HH];
__device__ float g_tmp [NN*HH];   // composite weights/biases live here
__device__ float g_h1  [NN*HH];
__device__ float g_h2  [NN*HH];
__device__ float g_hA  [NN*HH];
__device__ float g_hB  [NN*HH];
__device__ float g_gsum[GG*HH];   // later: O plane
__device__ float g_gvar[GG*HH];   // later: S plane
__device__ float g_gcnt[GG];

// ================= warp-MMA helpers (baseline PTX, sm_80+) =================
__device__ __forceinline__ void mma_bf16(float d[4], const uint32_t a[4], const uint32_t b[2]) {
    asm volatile(
        "mma.sync.aligned.m16n8k16.row.col.f32.bf16.bf16.f32 "
        "{%0,%1,%2,%3}, {%4,%5,%6,%7}, {%8,%9}, {%0,%1,%2,%3};"
        : "+f"(d[0]), "+f"(d[1]), "+f"(d[2]), "+f"(d[3])
        : "r"(a[0]), "r"(a[1]), "r"(a[2]), "r"(a[3]), "r"(b[0]), "r"(b[1]));
}

__device__ __forceinline__ void ldsm4(uint32_t r[4], uint32_t addr) {
    asm volatile("ldmatrix.sync.aligned.m8n8.x4.shared.b16 {%0,%1,%2,%3}, [%4];"
        : "=r"(r[0]), "=r"(r[1]), "=r"(r[2]), "=r"(r[3]) : "r"(addr));
}

__device__ __forceinline__ uint32_t smaddr(const void* p) {
    return (uint32_t)__cvta_generic_to_shared(p);
}

__device__ __forceinline__ void red_add_v2(float* p, float2 v) {
    asm volatile("red.global.add.v2.f32 [%0], {%1,%2};"
        :: "l"(p), "f"(v.x), "f"(v.y) : "memory");
}

__device__ __forceinline__ void split_bf16(float f, __nv_bfloat16& h, __nv_bfloat16& l) {
    h = __float2bfloat16_rn(f);
    l = __float2bfloat16_rn(f - __bfloat162float(h));
}

__device__ __forceinline__ void split_pack2(float f0, float f1, uint32_t& hi, uint32_t& lo) {
    __nv_bfloat16 h0, l0, h1, l1;
    split_bf16(f0, h0, l0);
    split_bf16(f1, h1, l1);
    hi = (uint32_t)__bfloat16_as_ushort(h0) | ((uint32_t)__bfloat16_as_ushort(h1) << 16);
    lo = (uint32_t)__bfloat16_as_ushort(l0) | ((uint32_t)__bfloat16_as_ushort(l1) << 16);
}

#define OFF_A(lane, stride) ((((lane) & 15) * (stride) + (((lane) >> 4) << 3)) * 2)
#define OFF_B(lane, stride) (((((lane) & 7) + (((lane) >> 4) << 3)) * (stride) + ((((lane) >> 3) & 1) << 3)) * 2)

// ---------------- edge kernel smem layout ----------------
template<int F> struct EL {
    static constexpr int KP  = (F + 15) & ~15;
    static constexpr int SA  = KP + 8;
    static constexpr int W1H = 0;
    static constexpr int W1L = W1H + 64 * SA * 2;
    static constexpr int W2H = W1L + 64 * SA * 2;
    static constexpr int W2L = W2H + 128 * 72 * 2;
    static constexpr int MIH = W2L + 128 * 72 * 2;
    static constexpr int MIL = MIH + 128 * 72 * 2;
    static constexpr int A1H = MIL + 128 * 72 * 2;
    static constexpr int A1L = A1H + 128 * SA * 2;
    static constexpr int IDX = A1L + 128 * SA * 2;
    static constexpr int TOT = IDX + 2048;
};

// ================= fused edge kernel (R14-proven) =================
template<int F, int NTHR, int MINB>
__global__ void __launch_bounds__(NTHR, MINB) edge_fused(
    const float* __restrict__ feat, const float* __restrict__ w1,
    const float* __restrict__ w2,   const float* __restrict__ xh,
    const int* __restrict__ src,    const int* __restrict__ dst,
    float* __restrict__ agg, int ntiles)
{
    using L = EL<F>;
    constexpr int MW = NTHR / 64;
    constexpr int RM = 128 / MW;
    constexpr int MT = RM / 16;

    extern __shared__ char smem[];
    __nv_bfloat16* w1h = (__nv_bfloat16*)(smem + L::W1H);
    __nv_bfloat16* w1l = (__nv_bfloat16*)(smem + L::W1L);
    __nv_bfloat16* w2h = (__nv_bfloat16*)(smem + L::W2H);
    __nv_bfloat16* w2l = (__nv_bfloat16*)(smem + L::W2L);
    __nv_bfloat16* mih = (__nv_bfloat16*)(smem + L::MIH);
    __nv_bfloat16* mil = (__nv_bfloat16*)(smem + L::MIL);
    __nv_bfloat16* a1h = (__nv_bfloat16*)(smem + L::A1H);
    __nv_bfloat16* a1l = (__nv_bfloat16*)(smem + L::A1L);
    int*           sidx= (int*)          (smem + L::IDX);

    const int tid  = threadIdx.x;
    const int wid  = tid >> 5, lane = tid & 31;
    const int g    = lane >> 2, tq = lane & 3;
    const int wm   = wid & (MW - 1), wn = wid / MW;

    const uint32_t bA1h = smaddr(a1h), bA1l = smaddr(a1l);
    const uint32_t bW1h = smaddr(w1h), bW1l = smaddr(w1l);
    const uint32_t bW2h = smaddr(w2h), bW2l = smaddr(w2l);
    const uint32_t bMih = smaddr(mih), bMil = smaddr(mil);
    const int oA_SA = OFF_A(lane, L::SA), oB_SA = OFF_B(lane, L::SA);
    const int oA_72 = OFF_A(lane, 72),    oB_72 = OFF_B(lane, 72);

    for (int i = tid; i < L::TOT / 4; i += NTHR)
        reinterpret_cast<uint32_t*>(smem)[i] = 0;
    __syncthreads();

    for (int i = tid; i < F * 64; i += NTHR) {
        int k = i >> 6, n = i & 63;
        __nv_bfloat16 h, l; split_bf16(w1[i], h, l);
        w1h[n * L::SA + k] = h;  w1l[n * L::SA + k] = l;
    }
    for (int i = tid; i < 32 * 128; i += NTHR) {
        int n = i & 127, k = (i >> 7) * 2;
        uint32_t hi, lo;
        split_pack2(w2[k * 128 + n], w2[(k + 1) * 128 + n], hi, lo);
        *reinterpret_cast<uint32_t*>(&w2h[n * 72 + k]) = hi;
        *reinterpret_cast<uint32_t*>(&w2l[n * 72 + k]) = lo;
    }

    auto stage = [&](int tt, int parity) {
        if (tt >= ntiles) return;
        const int se0 = tt * 128;
        const int scnt = min(128, EE - se0);
        const float* fb = feat + (size_t)se0 * F;
        int* sx = sidx + parity * 256;
        if (scnt == 128) {
            constexpr int NIT = (128 * F + NTHR - 1) / NTHR;
            #pragma unroll
            for (int j = 0; j < NIT; ++j) {
                int i = tid + j * NTHR;
                if (128 * F % NTHR == 0 || i < 128 * F) {
                    int e = i / F, k = i - e * F;
                    __nv_bfloat16 h, l; split_bf16(fb[i], h, l);
                    a1h[e * L::SA + k] = h;  a1l[e * L::SA + k] = l;
                }
            }
            if (tid < 128) { sx[tid] = src[se0 + tid]; sx[128 + tid] = dst[se0 + tid]; }
        } else {
            for (int i = tid; i < scnt * F; i += NTHR) {
                int e = i / F, k = i - e * F;
                __nv_bfloat16 h, l; split_bf16(fb[i], h, l);
                a1h[e * L::SA + k] = h;  a1l[e * L::SA + k] = l;
            }
            if (tid < scnt) { sx[tid] = src[se0 + tid]; sx[128 + tid] = dst[se0 + tid]; }
        }
    };

    int t = blockIdx.x, pb = 0;
    stage(t, 0);
    __syncthreads();

    for (; t < ntiles; t += gridDim.x) {
        const int cnt = min(128, EE - t * 128);
        const int* sx = sidx + pb * 256;

        // ---- GEMM1 ----
        {
            const int mo = wm * RM, no = wn * 32;
            float acc[MT][4][4];
            #pragma unroll
            for (int a = 0; a < MT; ++a)
                #pragma unroll
                for (int b = 0; b < 4; ++b)
                    #pragma unroll
                    for (int c = 0; c < 4; ++c) acc[a][b][c] = 0.f;

            #pragma unroll
            for (int ko = 0; ko < L::KP; ko += 16) {
                uint32_t Ah[MT][4], Al[MT][4];
                #pragma unroll
                for (int mt = 0; mt < MT; ++mt) {
                    const int rb2 = ((mo + mt*16) * L::SA + ko) * 2;
                    ldsm4(Ah[mt], bA1h + rb2 + oA_SA);
                    ldsm4(Al[mt], bA1l + rb2 + oA_SA);
                }
                uint32_t Bh[4][2], Bl[4][2];
                #pragma unroll
                for (int p = 0; p < 2; ++p) {
                    const int nb2 = ((no + p*16) * L::SA + ko) * 2;
                    uint32_t tr[4];
                    ldsm4(tr, bW1h + nb2 + oB_SA);
                    Bh[2*p][0]=tr[0]; Bh[2*p][1]=tr[1]; Bh[2*p+1][0]=tr[2]; Bh[2*p+1][1]=tr[3];
                    ldsm4(tr, bW1l + nb2 + oB_SA);
                    Bl[2*p][0]=tr[0]; Bl[2*p][1]=tr[1]; Bl[2*p+1][0]=tr[2]; Bl[2*p+1][1]=tr[3];
                }
                #pragma unroll
                for (int nt = 0; nt < 4; ++nt)
                    #pragma unroll
                    for (int mt = 0; mt < MT; ++mt) {
                        mma_bf16(acc[mt][nt], Ah[mt], Bh[nt]);
                        mma_bf16(acc[mt][nt], Ah[mt], Bl[nt]);
                        mma_bf16(acc[mt][nt], Al[mt], Bh[nt]);
                    }
            }
            #pragma unroll
            for (int mt = 0; mt < MT; ++mt)
                #pragma unroll
                for (int nt = 0; nt < 4; ++nt) {
                    int r0 = mo + mt*16 + g, col = no + nt*8 + tq*2;
                    uint32_t hi, lo;
                    split_pack2(acc[mt][nt][0], acc[mt][nt][1], hi, lo);
                    *reinterpret_cast<uint32_t*>(&mih[r0*72 + col]) = hi;
                    *reinterpret_cast<uint32_t*>(&mil[r0*72 + col]) = lo;
                    split_pack2(acc[mt][nt][2], acc[mt][nt][3], hi, lo);
                    *reinterpret_cast<uint32_t*>(&mih[(r0+8)*72 + col]) = hi;
                    *reinterpret_cast<uint32_t*>(&mil[(r0+8)*72 + col]) = lo;
                }
        }
        __syncthreads();

        // ---- GEMM2 (K=64) ----
        float acc[MT][8][4];
        {
            const int mo = wm * RM, no = wn * 64;
            #pragma unroll
            for (int a = 0; a < MT; ++a)
                #pragma unroll
                for (int b = 0; b < 8; ++b)
                    #pragma unroll
                    for (int c = 0; c < 4; ++c) acc[a][b][c] = 0.f;

            #pragma unroll
            for (int ko = 0; ko < 64; ko += 16) {
                uint32_t Ah[MT][4], Al[MT][4];
                #pragma unroll
                for (int mt = 0; mt < MT; ++mt) {
                    const int rb2 = ((mo + mt*16) * 72 + ko) * 2;
                    ldsm4(Ah[mt], bMih + rb2 + oA_72);
                    ldsm4(Al[mt], bMil + rb2 + oA_72);
                }
                uint32_t Bh[8][2], Bl[8][2];
                #pragma unroll
                for (int p = 0; p < 4; ++p) {
                    const int nb2 = ((no + p*16) * 72 + ko) * 2;
                    uint32_t tr[4];
                    ldsm4(tr, bW2h + nb2 + oB_72);
                    Bh[2*p][0]=tr[0]; Bh[2*p][1]=tr[1]; Bh[2*p+1][0]=tr[2]; Bh[2*p+1][1]=tr[3];
                    ldsm4(tr, bW2l + nb2 + oB_72);
                    Bl[2*p][0]=tr[0]; Bl[2*p][1]=tr[1]; Bl[2*p+1][0]=tr[2]; Bl[2*p+1][1]=tr[3];
                }
                #pragma unroll
                for (int nt = 0; nt < 8; ++nt)
                    #pragma unroll
                    for (int mt = 0; mt < MT; ++mt) {
                        mma_bf16(acc[mt][nt], Ah[mt], Bh[nt]);
                        mma_bf16(acc[mt][nt], Ah[mt], Bl[nt]);
                        mma_bf16(acc[mt][nt], Al[mt], Bh[nt]);
                    }
            }
        }

        // ---- direct register epilogue ----
        {
            const int no = wn * 64, cb = no + tq * 2;
            #pragma unroll
            for (int mt = 0; mt < MT; ++mt) {
                #pragma unroll
                for (int hf = 0; hf < 2; ++hf) {
                    int e = wm * RM + mt*16 + g + hf*8;
                    if (e < cnt) {
                        int s = sx[e], d = sx[128 + e];
                        const float* xrow = xh + (size_t)s * 128 + cb;
                        float* arow = agg + (size_t)d * 128 + cb;
                        float2 xv[8];
                        #pragma unroll
                        for (int nt = 0; nt < 8; ++nt)
                            xv[nt] = *reinterpret_cast<const float2*>(xrow + nt*8);
                        #pragma unroll
                        for (int nt = 0; nt < 8; ++nt)
                            red_add_v2(arow + nt*8,
                                make_float2(acc[mt][nt][hf*2] * xv[nt].x,
                                            acc[mt][nt][hf*2+1] * xv[nt].y));
                    }
                }
            }
        }

        stage(t + gridDim.x, pb ^ 1);
        __syncthreads();
        pb ^= 1;
    }
}

// ================= node GEMM on HMMA (GN = fused S*h+O affine in staging) ====
template<bool HAS_A2, bool ACT, bool HAS_RES, bool DB, bool GN>
__global__ void __launch_bounds__(512) node_hmma(
    const float* __restrict__ A,  const float* __restrict__ W,
    const float* __restrict__ A2, const float* __restrict__ W2,
    const float* __restrict__ bias, const float* __restrict__ res,
    const int* __restrict__ batchv, const float* __restrict__ Spl,
    const float* __restrict__ Opl,
    float* __restrict__ out, int nrows, int ntiles)
{
    static_assert(!(HAS_A2 && DB), "DB only for single-A variant");
    constexpr int WS = 128 * 136 * 2;
    constexpr int NWP = HAS_A2 ? 4 : 2;
    constexpr int NAP = DB ? 4 : 2;
    extern __shared__ char smem[];
    __nv_bfloat16* wh  = (__nv_bfloat16*)(smem);
    __nv_bfloat16* wl  = (__nv_bfloat16*)(smem + WS);
    __nv_bfloat16* w2h = (__nv_bfloat16*)(smem + 2 * WS);
    __nv_bfloat16* w2l = (__nv_bfloat16*)(smem + 3 * WS);
    float*         bs  = (float*)        (smem + (NWP + NAP) * WS);

    const int tid = threadIdx.x;
    const int wid = tid >> 5, lane = tid & 31;
    const int g = lane >> 2, tq = lane & 3;
    const int wm = wid & 7, wn = wid >> 3;
    const int mo = wm * 16, no = wn * 64;
    const int oA = OFF_A(lane, 136), oB = OFF_B(lane, 136);

    for (int i = tid; i < 64 * 128; i += 512) {
        int n = i & 127, k = (i >> 7) * 2;
        uint32_t hi, lo;
        split_pack2(W[k * 128 + n], W[(k + 1) * 128 + n], hi, lo);
        *reinterpret_cast<uint32_t*>(&wh[n * 136 + k]) = hi;
        *reinterpret_cast<uint32_t*>(&wl[n * 136 + k]) = lo;
        if (HAS_A2) {
            split_pack2(W2[k * 128 + n], W2[(k + 1) * 128 + n], hi, lo);
            *reinterpret_cast<uint32_t*>(&w2h[n * 136 + k]) = hi;
            *reinterpret_cast<uint32_t*>(&w2l[n * 136 + k]) = lo;
        }
    }
    if (tid < 128) bs[tid] = bias[tid];

    auto a_hi = [&](int p) { return (__nv_bfloat16*)(smem + (NWP + p * 2) * WS); };
    auto a_lo = [&](int p) { return (__nv_bfloat16*)(smem + (NWP + p * 2 + 1) * WS); };

    auto stageA = [&](const float* __restrict__ src_, int tt, int p) {
        if (tt >= ntiles) return;
        const int rb = tt * 128;
        __nv_bfloat16* dh = a_hi(p);
        __nv_bfloat16* dl = a_lo(p);
        #pragma unroll 8
        for (int i = tid; i < 128 * 64; i += 512) {
            int e = i >> 6, kp = (i & 63) * 2;
            int r = rb + e;
            float2 v = (r < nrows) ? *reinterpret_cast<const float2*>(&src_[(size_t)r * 128 + kp])
                                   : make_float2(0.f, 0.f);
            if (GN) {
                if (r < nrows) {
                    int b = batchv[r];
                    float2 Sv = *reinterpret_cast<const float2*>(&Spl[b * 128 + kp]);
                    float2 Ov = *reinterpret_cast<const float2*>(&Opl[b * 128 + kp]);
                    v.x = Sv.x * v.x + Ov.x;
                    v.y = Sv.y * v.y + Ov.y;
                }
            }
            uint32_t hi, lo; split_pack2(v.x, v.y, hi, lo);
            *reinterpret_cast<uint32_t*>(&dh[e * 136 + kp]) = hi;
            *reinterpret_cast<uint32_t*>(&dl[e * 136 + kp]) = lo;
        }
    };

    auto run_mma = [&](float acc[8][4], const __nv_bfloat16* ahp, const __nv_bfloat16* alp,
                       const __nv_bfloat16* bhp, const __nv_bfloat16* blp) {
        const uint32_t bAh = smaddr(ahp), bAl = smaddr(alp);
        const uint32_t bBh = smaddr(bhp), bBl = smaddr(blp);
        #pragma unroll
        for (int ko = 0; ko < 128; ko += 16) {
            uint32_t Ah[4], Al[4];
            const int rb2 = (mo * 136 + ko) * 2;
            ldsm4(Ah, bAh + rb2 + oA);
            ldsm4(Al, bAl + rb2 + oA);
            #pragma unroll
            for (int p = 0; p < 4; ++p) {
                const int nb2 = ((no + p*16) * 136 + ko) * 2;
                uint32_t th[4], tl[4];
                ldsm4(th, bBh + nb2 + oB);
                ldsm4(tl, bBl + nb2 + oB);
                uint32_t B0h[2] = {th[0], th[1]}, B1h[2] = {th[2], th[3]};
                uint32_t B0l[2] = {tl[0], tl[1]}, B1l[2] = {tl[2], tl[3]};
                mma_bf16(acc[2*p],   Ah, B0h);
                mma_bf16(acc[2*p],   Ah, B0l);
                mma_bf16(acc[2*p],   Al, B0h);
                mma_bf16(acc[2*p+1], Ah, B1h);
                mma_bf16(acc[2*p+1], Ah, B1l);
                mma_bf16(acc[2*p+1], Al, B1h);
            }
        }
    };

    auto epilogue = [&](float acc[8][4], int rb) {
        #pragma unroll
        for (int nt = 0; nt < 8; ++nt) {
            const int c = no + nt*8 + tq*2;
            const float b0 = bs[c], b1 = bs[c + 1];
            #pragma unroll
            for (int half = 0; half < 2; ++half) {
                int r = rb + mo + g + half*8;
                if (r < nrows) {
                    float v0 = acc[nt][half*2]     + b0;
                    float v1 = acc[nt][half*2 + 1] + b1;
                    if (ACT) { v0 = v0 / (1.f + expf(-v0)); v1 = v1 / (1.f + expf(-v1)); }
                    if (HAS_RES) {
                        float2 rr = *reinterpret_cast<const float2*>(&res[(size_t)r*128 + c]);
                        v0 += rr.x; v1 += rr.y;
                    }
                    *reinterpret_cast<float2*>(&out[(size_t)r*128 + c]) = make_float2(v0, v1);
                }
            }
        }
    };

    if (DB) {
        int t = blockIdx.x, pb = 0;
        stageA(A, t, 0);
        __syncthreads();
        for (; t < ntiles; t += gridDim.x) {
            float acc[8][4];
            #pragma unroll
            for (int b = 0; b < 8; ++b)
                #pragma unroll
                for (int c = 0; c < 4; ++c) acc[b][c] = 0.f;
            run_mma(acc, a_hi(pb), a_lo(pb), wh, wl);
            stageA(A, t + gridDim.x, pb ^ 1);
            epilogue(acc, t * 128);
            pb ^= 1;
            __syncthreads();
        }
    } else {
        __syncthreads();
        for (int t = blockIdx.x; t < ntiles; t += gridDim.x) {
            stageA(A, t, 0);
            __syncthreads();
            float acc[8][4];
            #pragma unroll
            for (int b = 0; b < 8; ++b)
                #pragma unroll
                for (int c = 0; c < 4; ++c) acc[b][c] = 0.f;
            run_mma(acc, a_hi(0), a_lo(0), wh, wl);
            if (HAS_A2) {
                __syncthreads();
                stageA(A2, t, 0);
                __syncthreads();
                run_mma(acc, a_hi(0), a_lo(0), w2h, w2l);
            }
            epilogue(acc, t * 128);
            __syncthreads();
        }
    }
}

// ================= composite weights: blocks 0-3: O = A@B; 4-5: o = a@B + c ==========
__global__ void __launch_bounds__(512) compose_kernel(
    const float* __restrict__ c1_rel_w, const float* __restrict__ c1_root_w,
    const float* __restrict__ lin1_w,
    const float* __restrict__ c2_rel_w, const float* __restrict__ c2_root_w,
    const float* __restrict__ lin2_w,
    const float* __restrict__ c1_rel_b, const float* __restrict__ lin1_b,
    const float* __restrict__ c2_rel_b, const float* __restrict__ lin2_b,
    float* __restrict__ Wa1, float* __restrict__ Wx1,
    float* __restrict__ Wa2, float* __restrict__ Wx2,
    float* __restrict__ b1p, float* __restrict__ b2p)
{
    const int bt = blockIdx.x;
    if (bt < 4) {
        const float* A = (bt == 0) ? c1_rel_w : (bt == 1) ? c1_root_w
                        : (bt == 2) ? c2_rel_w : c2_root_w;
        const float* B = (bt < 2) ? lin1_w : lin2_w;
        float* O = (bt == 0) ? Wa1 : (bt == 1) ? Wx1 : (bt == 2) ? Wa2 : Wx2;

        extern __shared__ float s[];
        float* sA  = s;                 // 128*128 (row-major, k contiguous)
        float* sBt = s + 16384;         // 128*132 (transposed: [n][k], k contiguous)
        for (int i = threadIdx.x; i < 16384; i += 512) {
            sA[i] = A[i];
            int k = i >> 7, n = i & 127;
            sBt[n * 132 + k] = B[i];
        }
        __syncthreads();

        const int n = threadIdx.x & 127, rg = threadIdx.x >> 7;   // 4 groups x 32 rows
        float acc[32];
        #pragma unroll
        for (int i = 0; i < 32; ++i) acc[i] = 0.f;
        for (int k = 0; k < 128; k += 4) {
            float4 bv = *reinterpret_cast<const float4*>(&sBt[n * 132 + k]);
            #pragma unroll
            for (int i = 0; i < 32; ++i) {
                float4 av = *reinterpret_cast<const float4*>(&sA[(rg*32 + i) * 128 + k]);
                acc[i] += av.x*bv.x + av.y*bv.y + av.z*bv.z + av.w*bv.w;
            }
        }
        #pragma unroll
        for (int i = 0; i < 32; ++i) O[(rg*32 + i) * 128 + n] = acc[i];
    } else {
        const float* a = (bt == 4) ? c1_rel_b : c2_rel_b;
        const float* B = (bt == 4) ? lin1_w : lin2_w;
        const float* c = (bt == 4) ? lin1_b : lin2_b;
        float* O = (bt == 4) ? b1p : b2p;
        if (threadIdx.x < 128) {
            int n = threadIdx.x;
            float s2 = c[n];
            for (int k = 0; k < 128; ++k) s2 += a[k] * B[k * 128 + n];
            O[n] = s2;
        }
    }
}

// ---------------- zero init ----------------
__global__ void zero_bufs_kernel() {
    int idx = blockIdx.x * blockDim.x + threadIdx.x;
    if (idx < NN*HH) { g_agg1[idx] = 0.f; g_agg2[idx] = 0.f; }
    if (idx < GG*HH) { g_gsum[idx] = 0.f; g_gvar[idx] = 0.f; }
    if (idx < GG)    { g_gcnt[idx] = 0.f; }
}

// ---------------- GraphNorm: segmented reductions (batch is sorted) ----------------
__global__ void __launch_bounds__(128) gn_accum_seg(
    const float* __restrict__ h, const int* __restrict__ batch)
{
    const int n0 = blockIdx.x * 64;
    const int c  = threadIdx.x;
    const int nend = min(n0 + 64, NN);
    int   cur = batch[n0];
    float run = 0.f, runc = 0.f;
    for (int n = n0; n < nend; ++n) {
        int b = batch[n];
        if (b != cur) {
            atomicAdd(&g_gsum[cur*128 + c], run);
            if (c == 0) atomicAdd(&g_gcnt[cur], runc);
            run = 0.f; runc = 0.f; cur = b;
        }
        run  += h[(size_t)n*128 + c];
        runc += 1.f;
    }
    atomicAdd(&g_gsum[cur*128 + c], run);
    if (c == 0) atomicAdd(&g_gcnt[cur], runc);
}

__global__ void __launch_bounds__(128) gn_var_seg(
    const float* __restrict__ h, const int* __restrict__ batch,
    const float* __restrict__ ms)
{
    const int n0 = blockIdx.x * 64;
    const int c  = threadIdx.x;
    const int nend = min(n0 + 64, NN);
    const float msc = ms[c];
    int   cur = batch[n0];
    float mean = g_gsum[cur*128 + c] / fmaxf(g_gcnt[cur], 1.f);
    float run = 0.f;
    for (int n = n0; n < nend; ++n) {
        int b = batch[n];
        if (b != cur) {
            atomicAdd(&g_gvar[cur*128 + c], run);
            run = 0.f; cur = b;
            mean = g_gsum[cur*128 + c] / fmaxf(g_gcnt[cur], 1.f);
        }
        float o = h[(size_t)n*128 + c] - mean * msc;
        run += o * o;
    }
    atomicAdd(&g_gvar[cur*128 + c], run);
}

__global__ void gn_affine(const float* __restrict__ ms,
                          const float* __restrict__ nw, const float* __restrict__ nb)
{
    int idx = blockIdx.x * blockDim.x + threadIdx.x;
    if (idx >= GG*HH) return;
    int b = idx >> 7, c = idx & 127;
    float cnt  = fmaxf(g_gcnt[b], 1.f);
    float mean = g_gsum[idx] / cnt;
    float istd = rsqrtf(g_gvar[idx] / cnt + EPSV);
    float S = nw[c] * istd;
    g_gvar[idx] = S;
    g_gsum[idx] = nb[c] - S * mean * ms[c];
}

// ---------------- host launcher ----------------
static inline void set_smem(const void* f, int bytes) {
    cudaFuncSetAttribute(f, cudaFuncAttributeMaxDynamicSharedMemorySize, bytes);
}

extern "C" void kernel_launch(void* const* d_in, const int* in_sizes, int n_in,
                              void* d_out, int out_size) {
    (void)in_sizes; (void)n_in; (void)out_size;

    const float* x          = (const float*)d_in[0];
    const float* feature1   = (const float*)d_in[1];
    const float* feature2   = (const float*)d_in[2];
    const int*   edge_index = (const int*)  d_in[3];
    const int*   batch      = (const int*)  d_in[4];
    const float* lin_w      = (const float*)d_in[5];
    const float* lin_b      = (const float*)d_in[6];
    const float* f1_w1      = (const float*)d_in[7];
    const float* f1_w2      = (const float*)d_in[8];
    const float* f2_w1      = (const float*)d_in[9];
    const float* f2_w2      = (const float*)d_in[10];
    const float* c1_rel_w   = (const float*)d_in[11];
    const float* c1_rel_b   = (const float*)d_in[12];
    const float* c1_root_w  = (const float*)d_in[13];
    const float* c2_rel_w   = (const float*)d_in[14];
    const float* c2_rel_b   = (const float*)d_in[15];
    const float* c2_root_w  = (const float*)d_in[16];
    const float* lin1_w     = (const float*)d_in[17];
    const float* lin1_b     = (const float*)d_in[18];
    const float* lin2_w     = (const float*)d_in[19];
    const float* lin2_b     = (const float*)d_in[20];
    const float* lincat_w   = (const float*)d_in[21];
    const float* lincat_b   = (const float*)d_in[22];
    const float* norm_w     = (const float*)d_in[23];
    const float* norm_b     = (const float*)d_in[24];
    const float* norm_ms    = (const float*)d_in[25];
    const float* lins_w     = (const float*)d_in[26];
    const float* lins_b     = (const float*)d_in[27];
    const float* final_w    = (const float*)d_in[28];
    const float* final_b    = (const float*)d_in[29];
    float* out = (float*)d_out;

    const int* src = edge_index;
    const int* dst = edge_index + EE;

    float *xh, *agg1, *agg2, *tmp, *h1, *h2, *hA, *hB, *gvar, *gsum;
    cudaGetSymbolAddress((void**)&xh,   g_xh);
    cudaGetSymbolAddress((void**)&agg1, g_agg1);
    cudaGetSymbolAddress((void**)&agg2, g_agg2);
    cudaGetSymbolAddress((void**)&tmp,  g_tmp);
    cudaGetSymbolAddress((void**)&h1,   g_h1);
    cudaGetSymbolAddress((void**)&h2,   g_h2);
    cudaGetSymbolAddress((void**)&hA,   g_hA);
    cudaGetSymbolAddress((void**)&hB,   g_hB);
    cudaGetSymbolAddress((void**)&gvar, g_gvar);
    cudaGetSymbolAddress((void**)&gsum, g_gsum);

    // composite weight/bias storage inside g_tmp
    float* Wa1 = tmp;
    float* Wx1 = tmp + 16384;
    float* Wa2 = tmp + 32768;
    float* Wx2 = tmp + 49152;
    float* b1p = tmp + 65536;
    float* b2p = tmp + 65664;

    constexpr int WS = 128 * 136 * 2;
    const int N1 = 6 * WS + 512;
    const int N2 = 6 * WS + 512;
    const int CSM = (16384 + 128 * 132) * 4;   // 133,120 B

    set_smem((const void*)node_hmma<false,true ,false,true ,false>, N1);
    set_smem((const void*)node_hmma<false,true ,true ,true ,false>, N1);
    set_smem((const void*)node_hmma<false,false,false,true ,true >, N1);
    set_smem((const void*)node_hmma<true ,true ,false,false,false>, N2);
    set_smem((const void*)node_hmma<true ,false,true ,false,false>, N2);
    set_smem((const void*)edge_fused<FF1,512,1>, EL<FF1>::TOT);
    set_smem((const void*)edge_fused<FF2,256,2>, EL<FF2>::TOT);
    set_smem((const void*)compose_kernel, CSM);

    const int EL_GRID = (NN*HH + 255) / 256;
    const int GH_GRID = (GG*HH + 255) / 256;
    const int SEG_GRID = (NN + 63) / 64;
    const int NT      = (EE + 127) / 128;
    const int NTN     = (NN + 127) / 128;

    // 0) zero accumulators + composite weights (independent, early)
    zero_bufs_kernel<<<EL_GRID, 256>>>();
    compose_kernel<<<6, 512, CSM>>>(
        c1_rel_w, c1_root_w, lin1_w, c2_rel_w, c2_root_w, lin2_w,
        c1_rel_b, lin1_b, c2_rel_b, lin2_b,
        Wa1, Wx1, Wa2, Wx2, b1p, b2p);

    // 1) xh = swish(x @ lin_w + lin_b)
    node_hmma<false,true,false,true,false><<<148, 512, N1>>>(
        x, lin_w, nullptr, nullptr, lin_b, nullptr,
        nullptr, nullptr, nullptr, xh, NN, NTN);

    // 2) fused edge messages
    edge_fused<FF1,512,1><<<148, 512, EL<FF1>::TOT>>>(feature1, f1_w1, f1_w2, xh, src, dst, agg1, NT);
    edge_fused<FF2,256,2><<<296, 256, EL<FF2>::TOT>>>(feature2, f2_w1, f2_w2, xh, src, dst, agg2, NT);

    // 3) conv1+lin1 fused via composite weights: h1 = swish(agg1@Wa1 + xh@Wx1 + b1')
    node_hmma<true,true,false,false,false><<<148, 512, N2>>>(
        agg1, Wa1, xh, Wx1, b1p, nullptr,
        nullptr, nullptr, nullptr, h1, NN, NTN);

    // 4) conv2+lin2 fused: h2 = swish(agg2@Wa2 + xh@Wx2 + b2')
    node_hmma<true,true,false,false,false><<<148, 512, N2>>>(
        agg2, Wa2, xh, Wx2, b2p, nullptr,
        nullptr, nullptr, nullptr, h2, NN, NTN);

    // 5) hA = h1@Wtop + h2@Wbot + lincat_b + xh
    node_hmma<true,false,true,false,false><<<148, 512, N2>>>(
        h1, lincat_w, h2, lincat_w + 128*128, lincat_b, xh,
        nullptr, nullptr, nullptr, hA, NN, NTN);

    // 6) residual stack
    node_hmma<false,true,true,true,false><<<148, 512, N1>>>(
        hA, lins_w + 0*16384, nullptr, nullptr, lins_b + 0*128, hA,
        nullptr, nullptr, nullptr, hB, NN, NTN);
    node_hmma<false,true,true,true,false><<<148, 512, N1>>>(
        hB, lins_w + 1*16384, nullptr, nullptr, lins_b + 1*128, hB,
        nullptr, nullptr, nullptr, hA, NN, NTN);
    node_hmma<false,true,true,true,false><<<148, 512, N1>>>(
        hA, lins_w + 2*16384, nullptr, nullptr, lins_b + 2*128, hA,
        nullptr, nullptr, nullptr, hB, NN, NTN);

    // 7) GraphNorm on hB (segmented; folded into per-(graph,col) affine)
    gn_accum_seg<<<SEG_GRID, 128>>>(hB, batch);
    gn_var_seg  <<<SEG_GRID, 128>>>(hB, batch, norm_ms);
    gn_affine   <<<GH_GRID, 256>>>(norm_ms, norm_w, norm_b);

    // 8) out = (S*hB + O) @ final_w + final_b
    node_hmma<false,false,false,true,true><<<148, 512, N1>>>(
        hB, final_w, nullptr, nullptr, final_b, nullptr,
        batch, gvar, gsum, out, NN, NTN);
}